// round 2
// baseline (speedup 1.0000x reference)
#include <cuda_runtime.h>
#include <math.h>

#define DIMC 256
#define NHEADS 8
#define HEADD 32
#define KEYD 16
#define HQKV 512
#define NB 16
#define NPIX 1024
#define EPSV 1e-5f
#define ATTN_SCALE 0.25f   // KEY_DIM^-0.5 = 16^-0.5

// Scratch (allocation-free rule: __device__ globals)
__device__ float g_qkv_buf[(size_t)NB * HQKV * NPIX];   // 33.5 MB: qkv[b][o][p]
__device__ float g_att_buf[(size_t)NB * DIMC * NPIX];   // 16.8 MB: attended(+pos)[b][c][p]

// ---------------------------------------------------------------------------
// Generic fp32 GEMM + BatchNorm epilogue:
//   out[b][o][p] = BN( sum_c A[o][c] * In[b][c][p] )
// A: [M x 256] row-major.  In: per-batch stride 256*1024.  Out: stride M*1024.
// Tiles: BM=64 (o), BN=64 (p), BK=16. 256 threads, 4x4 microtile.
// ---------------------------------------------------------------------------
__global__ void gemm_bn_kernel(const float* __restrict__ A,
                               const float* __restrict__ In,
                               float* __restrict__ Out,
                               int M,
                               const float* __restrict__ gam,
                               const float* __restrict__ bet,
                               const float* __restrict__ mu,
                               const float* __restrict__ var) {
    __shared__ float As[16][68];   // [k][o], padded
    __shared__ float Bs[16][64];   // [k][p]

    const int b = blockIdx.z;
    const int oBase = blockIdx.y * 64;
    const int pBase = blockIdx.x * 64;
    const int tid = threadIdx.x;          // 0..255
    const int tx = tid & 15;              // p microtile
    const int ty = tid >> 4;              // o microtile

    const float* inb = In + (size_t)b * DIMC * NPIX;

    float acc[4][4];
#pragma unroll
    for (int i = 0; i < 4; i++)
#pragma unroll
        for (int j = 0; j < 4; j++) acc[i][j] = 0.f;

    for (int k0 = 0; k0 < DIMC; k0 += 16) {
        // Load A tile [64 x 16] -> As[k][o] (transpose)
        {
            int row = tid >> 2;            // 0..63 (o)
            int col4 = (tid & 3) * 4;      // 0,4,8,12 (k)
            float4 wv = *(const float4*)&A[(size_t)(oBase + row) * DIMC + k0 + col4];
            As[col4 + 0][row] = wv.x;
            As[col4 + 1][row] = wv.y;
            As[col4 + 2][row] = wv.z;
            As[col4 + 3][row] = wv.w;
        }
        // Load In tile [16 x 64] -> Bs[k][p]
        {
            int row = tid >> 4;            // 0..15 (k)
            int col4 = (tid & 15) * 4;     // p
            *(float4*)&Bs[row][col4] =
                *(const float4*)&inb[(size_t)(k0 + row) * NPIX + pBase + col4];
        }
        __syncthreads();
#pragma unroll
        for (int k = 0; k < 16; k++) {
            float a[4];
#pragma unroll
            for (int i = 0; i < 4; i++) a[i] = As[k][ty * 4 + i];
            float4 bv = *(const float4*)&Bs[k][tx * 4];
            float bb[4] = {bv.x, bv.y, bv.z, bv.w};
#pragma unroll
            for (int i = 0; i < 4; i++)
#pragma unroll
                for (int j = 0; j < 4; j++) acc[i][j] += a[i] * bb[j];
        }
        __syncthreads();
    }

    // Epilogue: BN affine, vectorized store
#pragma unroll
    for (int i = 0; i < 4; i++) {
        int o = oBase + ty * 4 + i;
        float inv = rsqrtf(var[o] + EPSV) * gam[o];
        float add = bet[o] - mu[o] * inv;
        float4 r;
        r.x = acc[i][0] * inv + add;
        r.y = acc[i][1] * inv + add;
        r.z = acc[i][2] * inv + add;
        r.w = acc[i][3] * inv + add;
        *(float4*)&Out[((size_t)b * M + o) * NPIX + pBase + tx * 4] = r;
    }
}

// ---------------------------------------------------------------------------
// Flash-style attention. One CTA per (b, head). K,V resident in smem.
// qkv head block layout (64 rows x 1024): rows 0-15 q, 16-31 k, 32-63 v.
// 256 threads; each thread owns 2 queries per pass, 2 passes.
// Online softmax in 16-key chunks.
// ---------------------------------------------------------------------------
__global__ void attn_kernel(const float* __restrict__ qkv,
                            float* __restrict__ att) {
    extern __shared__ float sm[];
    float* k_s = sm;                 // [16][1024]
    float* v_s = sm + 16 * NPIX;     // [32][1024]

    const int bh = blockIdx.x;
    const int b = bh >> 3;
    const int h = bh & 7;
    const float* base = qkv + ((size_t)b * HQKV + h * 64) * NPIX;
    const int tid = threadIdx.x;     // 0..255

    // Load k (rows 16..31) and v (rows 32..63): 48 rows contiguous
    {
        const float4* src = (const float4*)(base + 16 * NPIX);
        float4* dst = (float4*)sm;
        for (int i = tid; i < 48 * NPIX / 4; i += 256) dst[i] = src[i];
    }
    __syncthreads();

    float* ob = att + ((size_t)b * DIMC + h * HEADD) * NPIX;

    for (int iter = 0; iter < 2; iter++) {
        const int q0 = iter * 512 + tid;
        const int q1 = q0 + 256;

        float qa[16], qb[16];
#pragma unroll
        for (int c = 0; c < 16; c++) {
            qa[c] = base[c * NPIX + q0] * ATTN_SCALE;
            qb[c] = base[c * NPIX + q1] * ATTN_SCALE;
        }

        float m0 = -1e30f, m1 = -1e30f, l0 = 0.f, l1 = 0.f;
        float o0[32], o1[32];
#pragma unroll
        for (int d = 0; d < 32; d++) { o0[d] = 0.f; o1[d] = 0.f; }

        for (int kc = 0; kc < NPIX; kc += 16) {
            float s0[16], s1[16];
#pragma unroll
            for (int j = 0; j < 16; j++) {
                float a0 = 0.f, a1 = 0.f;
                const float* kcol = k_s + kc + j;
#pragma unroll
                for (int c = 0; c < 16; c++) {
                    float kv = kcol[c * NPIX];
                    a0 += qa[c] * kv;
                    a1 += qb[c] * kv;
                }
                s0[j] = a0;
                s1[j] = a1;
            }
            float cm0 = s0[0], cm1 = s1[0];
#pragma unroll
            for (int j = 1; j < 16; j++) {
                cm0 = fmaxf(cm0, s0[j]);
                cm1 = fmaxf(cm1, s1[j]);
            }
            float nm0 = fmaxf(m0, cm0), nm1 = fmaxf(m1, cm1);
            float al0 = __expf(m0 - nm0), al1 = __expf(m1 - nm1);
            m0 = nm0; m1 = nm1;
            l0 *= al0; l1 *= al1;
#pragma unroll
            for (int d = 0; d < 32; d++) { o0[d] *= al0; o1[d] *= al1; }
#pragma unroll
            for (int j = 0; j < 16; j++) {
                s0[j] = __expf(s0[j] - m0);   // reuse s regs as p
                s1[j] = __expf(s1[j] - m1);
                l0 += s0[j];
                l1 += s1[j];
            }
#pragma unroll
            for (int j = 0; j < 16; j++) {
                const float* vcol = v_s + kc + j;
                float p0 = s0[j], p1 = s1[j];
#pragma unroll
                for (int d = 0; d < 32; d++) {
                    float vv = vcol[d * NPIX];
                    o0[d] += p0 * vv;
                    o1[d] += p1 * vv;
                }
            }
        }

        float r0 = 1.f / l0, r1 = 1.f / l1;
#pragma unroll
        for (int d = 0; d < 32; d++) {
            ob[d * NPIX + q0] = o0[d] * r0;
            ob[d * NPIX + q1] = o1[d] * r1;
        }
    }
}

// ---------------------------------------------------------------------------
// Depthwise 3x3 conv on v_img + BN, added into attended buffer in-place.
// v_img channel ch maps to qkv channel (ch/32)*64 + 32 + (ch%32).
// ---------------------------------------------------------------------------
__global__ void pos_conv_kernel(const float* __restrict__ qkv,
                                float* __restrict__ att,
                                const float* __restrict__ wpos,
                                const float* __restrict__ gam,
                                const float* __restrict__ bet,
                                const float* __restrict__ mu,
                                const float* __restrict__ var) {
    int idx = blockIdx.x * blockDim.x + threadIdx.x;
    if (idx >= NB * DIMC * NPIX) return;
    int p = idx & 1023;
    int ch = (idx >> 10) & 255;
    int b = idx >> 18;
    int y = p >> 5, x = p & 31;
    int o = ((ch >> 5) * 64) + 32 + (ch & 31);
    const float* vrow = qkv + ((size_t)b * HQKV + o) * NPIX;
    const float* wp = wpos + ch * 9;

    float acc = 0.f;
#pragma unroll
    for (int dy = 0; dy < 3; dy++) {
        int yy = y + dy - 1;
        if (yy < 0 || yy > 31) continue;
#pragma unroll
        for (int dx = 0; dx < 3; dx++) {
            int xx = x + dx - 1;
            if (xx < 0 || xx > 31) continue;
            acc += vrow[yy * 32 + xx] * wp[dy * 3 + dx];
        }
    }
    float inv = rsqrtf(var[ch] + EPSV) * gam[ch];
    att[idx] += acc * inv + (bet[ch] - mu[ch] * inv);
}

// ---------------------------------------------------------------------------
extern "C" void kernel_launch(void* const* d_in, const int* in_sizes, int n_in,
                              void* d_out, int out_size) {
    const float* x      = (const float*)d_in[0];
    const float* w_qkv  = (const float*)d_in[1];
    const float* g_qkv  = (const float*)d_in[2];
    const float* b_qkv  = (const float*)d_in[3];
    const float* m_qkv  = (const float*)d_in[4];
    const float* v_qkv  = (const float*)d_in[5];
    const float* w_pos  = (const float*)d_in[6];
    const float* g_pos  = (const float*)d_in[7];
    const float* b_pos  = (const float*)d_in[8];
    const float* m_pos  = (const float*)d_in[9];
    const float* v_pos  = (const float*)d_in[10];
    const float* w_proj = (const float*)d_in[11];
    const float* g_proj = (const float*)d_in[12];
    const float* b_proj = (const float*)d_in[13];
    const float* m_proj = (const float*)d_in[14];
    const float* v_proj = (const float*)d_in[15];
    float* out = (float*)d_out;

    float* qkv_buf = nullptr;
    float* att_buf = nullptr;
    cudaGetSymbolAddress((void**)&qkv_buf, g_qkv_buf);
    cudaGetSymbolAddress((void**)&att_buf, g_att_buf);

    const int attn_smem = 48 * NPIX * sizeof(float);   // 192 KB
    cudaFuncSetAttribute(attn_kernel,
                         cudaFuncAttributeMaxDynamicSharedMemorySize, attn_smem);

    // 1) QKV GEMM + BN
    gemm_bn_kernel<<<dim3(NPIX / 64, HQKV / 64, NB), 256>>>(
        w_qkv, x, qkv_buf, HQKV, g_qkv, b_qkv, m_qkv, v_qkv);

    // 2) Attention -> att_buf
    attn_kernel<<<NB * NHEADS, 256, attn_smem>>>(qkv_buf, att_buf);

    // 3) Depthwise conv + BN, add into att_buf
    pos_conv_kernel<<<(NB * DIMC * NPIX) / 256, 256>>>(
        qkv_buf, att_buf, w_pos, g_pos, b_pos, m_pos, v_pos);

    // 4) Proj GEMM + BN -> d_out
    gemm_bn_kernel<<<dim3(NPIX / 64, DIMC / 64, NB), 256>>>(
        w_proj, att_buf, out, DIMC, g_proj, b_proj, m_proj, v_proj);
}